// round 7
// baseline (speedup 1.0000x reference)
#include <cuda_runtime.h>
#include <cuda_bf16.h>
#include <cstdint>

// Problem constants
#define B_  256
#define L_  500
#define E_  300
#define H_  10
#define K_  5

#define NT    512
#define NKS   19          // k-steps of 16 (covers 304, valid 300)
#define NNT   7           // n-tiles of 8 (56 cols, valid 50) -- tile 7 was all-dead padding

// shared memory layout (bytes)
#define SM_BHI   0
#define SM_BLO   (SM_BHI + NKS*NNT*64*4)     // 19*448*4 = 34048
#define SM_PROJ  (SM_BLO + NKS*NNT*64*4)     // 68096  (50*500*4 = 100000)
#define SM_SC    (SM_PROJ + 50*500*4)        // 168096 (2500*4 = 10000)
#define SM_AE    (SM_SC + K_*L_*4)           // 178096
#define SMEM_BYTES (SM_AE + 640)             // 178736

__device__ __forceinline__ uint32_t cvt_bf2(float lo, float hi) {
    uint32_t d;
    asm("cvt.rn.bf16x2.f32 %0, %1, %2;" : "=r"(d) : "f"(hi), "f"(lo));
    return d;
}
// residual pair after removing bf16 hi parts
__device__ __forceinline__ uint32_t cvt_bf2_lo(float2 v, uint32_t hi) {
    float h0 = __uint_as_float(hi << 16);
    float h1 = __uint_as_float(hi & 0xFFFF0000u);
    return cvt_bf2(v.x - h0, v.y - h1);
}

__device__ __forceinline__ void mma_bf16(float* d, const uint32_t* a,
                                         uint32_t b0, uint32_t b1) {
    asm volatile(
        "mma.sync.aligned.m16n8k16.row.col.f32.bf16.bf16.f32 "
        "{%0,%1,%2,%3}, {%4,%5,%6,%7}, {%8,%9}, {%0,%1,%2,%3};"
        : "+f"(d[0]), "+f"(d[1]), "+f"(d[2]), "+f"(d[3])
        : "r"(a[0]), "r"(a[1]), "r"(a[2]), "r"(a[3]), "r"(b0), "r"(b1));
}

__global__ __launch_bounds__(NT, 1)
void anr_arl_kernel(const float* __restrict__ review,
                    const float* __restrict__ aspProj,
                    const float* __restrict__ aspEmbed,
                    float* __restrict__ out)
{
    extern __shared__ char smc[];
    uint32_t* sBhi   = reinterpret_cast<uint32_t*>(smc + SM_BHI);
    uint32_t* sBlo   = reinterpret_cast<uint32_t*>(smc + SM_BLO);
    float*    sProj  = reinterpret_cast<float*>(smc + SM_PROJ);   // [kh*500 + l]
    float*    sScores= reinterpret_cast<float*>(smc + SM_SC);     // [k*500 + l]
    float*    sAE    = reinterpret_cast<float*>(smc + SM_AE);

    const int tid  = threadIdx.x;
    const int wid  = tid >> 5, lane = tid & 31;
    const int b    = blockIdx.x;
    const float* revB = review + (size_t)b * (L_ * E_);

    // ---- stage B fragments: [ks][nt][r][lane] u32 = bf16 pair (k0, k0+1) ----
    // B[k][n] = aspProj[n/10, k, n%10]; hi = bf16(w), lo = bf16(w - hi)
    for (int idx = tid; idx < NKS * NNT * 64; idx += NT) {
        int lan = idx & 31;
        int r   = (idx >> 5) & 1;
        int nt  = (idx >> 6) % NNT;
        int ks  = idx / (NNT * 64);
        int k0  = ks * 16 + ((lan & 3) << 1) + r * 8;
        int n   = nt * 8 + (lan >> 2);
        float w0 = 0.f, w1 = 0.f;
        if (n < 50) {
            int base = (n / H_) * (E_ * H_) + (n % H_);
            if (k0 < E_)     w0 = aspProj[base + k0 * H_];
            if (k0 + 1 < E_) w1 = aspProj[base + (k0 + 1) * H_];
        }
        uint32_t hi = cvt_bf2(w0, w1);
        float h0 = __uint_as_float(hi << 16);
        float h1 = __uint_as_float(hi & 0xFFFF0000u);
        uint32_t lo = cvt_bf2(w0 - h0, w1 - h1);
        sBhi[idx] = hi;
        sBlo[idx] = lo;
    }
    for (int i = tid; i < K_ * 3 * H_; i += NT) sAE[i] = aspEmbed[i];
    __syncthreads();

    // ---- GEMM mainloop: warp w owns rows [w*32, w*32+32), software-pipelined ----
    float acc[2][NNT][4];
#pragma unroll
    for (int t = 0; t < 2; t++)
#pragma unroll
        for (int nt = 0; nt < NNT; nt++)
#pragma unroll
            for (int c = 0; c < 4; c++) acc[t][nt][c] = 0.f;

    const int mrow0 = wid * 32;
    const int rquad = lane >> 2;          // 0..7
    const int cpair = (lane & 3) << 1;    // 0,2,4,6

    // precompute clamped row pointers (rows fixed per thread across k-steps)
    const float* rowp[4];
#pragma unroll
    for (int t = 0; t < 2; t++) {
        int r0 = mrow0 + t * 16 + rquad;
        int r1 = r0 + 8;
        rowp[t * 2]     = revB + (size_t)((r0 < L_) ? r0 : 0) * E_;
        rowp[t * 2 + 1] = revB + (size_t)((r1 < L_) ? r1 : 0) * E_;
    }

    auto load8 = [&](float2* v, int ks) {
        const int c0 = ks * 16 + cpair;
        const int c1 = c0 + 8;
        const float2 z = make_float2(0.f, 0.f);
#pragma unroll
        for (int t = 0; t < 2; t++) {
            v[t * 4 + 0] = *reinterpret_cast<const float2*>(rowp[t * 2] + c0);
            v[t * 4 + 1] = *reinterpret_cast<const float2*>(rowp[t * 2 + 1] + c0);
            v[t * 4 + 2] = (c1 < E_) ? *reinterpret_cast<const float2*>(rowp[t * 2] + c1) : z;
            v[t * 4 + 3] = (c1 < E_) ? *reinterpret_cast<const float2*>(rowp[t * 2 + 1] + c1) : z;
        }
    };

    float2 raw[8];
    load8(raw, 0);

#pragma unroll 1
    for (int ks = 0; ks < NKS; ks++) {
        // convert current prefetched A chunk
        uint32_t ah[2][4], al[2][4];
#pragma unroll
        for (int t = 0; t < 2; t++) {
#pragma unroll
            for (int j = 0; j < 4; j++) {
                float2 v = raw[t * 4 + j];
                ah[t][j] = cvt_bf2(v.x, v.y);
                al[t][j] = cvt_bf2_lo(v, ah[t][j]);
            }
        }
        // prefetch next k-step's A while MMAs run
        if (ks + 1 < NKS) load8(raw, ks + 1);

        const uint32_t* bh = sBhi + ks * (NNT * 64);
        const uint32_t* bl = sBlo + ks * (NNT * 64);
#pragma unroll
        for (int nt = 0; nt < NNT; nt++) {
            uint32_t b0h = bh[(nt * 2 + 0) * 32 + lane];
            uint32_t b1h = bh[(nt * 2 + 1) * 32 + lane];
            uint32_t b0l = bl[(nt * 2 + 0) * 32 + lane];
            uint32_t b1l = bl[(nt * 2 + 1) * 32 + lane];
#pragma unroll
            for (int t = 0; t < 2; t++) {
                mma_bf16(acc[t][nt], ah[t], b0h, b1h);   // hi*hi
                mma_bf16(acc[t][nt], ah[t], b0l, b1l);   // hi*lo
                mma_bf16(acc[t][nt], al[t], b0h, b1h);   // lo*hi
            }
        }
    }

    // ---- writeback acc -> sProj[kh][l] ----
#pragma unroll
    for (int t = 0; t < 2; t++) {
#pragma unroll
        for (int nt = 0; nt < NNT; nt++) {
#pragma unroll
            for (int c = 0; c < 4; c++) {
                int row = mrow0 + t * 16 + rquad + ((c >> 1) ? 8 : 0);
                int col = nt * 8 + cpair + (c & 1);
                if (row < L_ && col < 50)
                    sProj[col * L_ + row] = acc[t][nt][c];
            }
        }
    }
    __syncthreads();

    // ---- window-3 attention scores: scores[k][l] ----
    for (int idx = tid; idx < K_ * L_; idx += NT) {
        int k = idx / L_, l = idx - k * L_;
        const float* aEk = sAE + k * 3 * H_;
        const float* pk  = sProj + k * H_ * L_;
        float s = 0.f;
#pragma unroll
        for (int i = 0; i < 3; i++) {
            int ll = l - 1 + i;
            if ((unsigned)ll < (unsigned)L_) {
#pragma unroll
                for (int h = 0; h < H_; h++)
                    s += pk[h * L_ + ll] * aEk[h * 3 + i];
            }
        }
        sScores[idx] = s;
    }
    __syncthreads();

    // ---- softmax over l per k (warp k), write attn out (B,K,L) ----
    if (wid < K_) {
        float* srow = sScores + wid * L_;
        float m = -3.402823466e38f;
        for (int l = lane; l < L_; l += 32) m = fmaxf(m, srow[l]);
#pragma unroll
        for (int o = 16; o > 0; o >>= 1) m = fmaxf(m, __shfl_xor_sync(0xffffffffu, m, o));
        float ssum = 0.f;
        for (int l = lane; l < L_; l += 32) {
            float ev = expf(srow[l] - m);
            srow[l] = ev;
            ssum += ev;
        }
#pragma unroll
        for (int o = 16; o > 0; o >>= 1) ssum += __shfl_xor_sync(0xffffffffu, ssum, o);
        float inv = 1.0f / ssum;
        float* oa = out + (size_t)b * (K_ * L_) + wid * L_;
        for (int l = lane; l < L_; l += 32) {
            float a = srow[l] * inv;
            srow[l] = a;          // keep normalized attn for pooling
            oa[l] = a;
        }
    }
    __syncthreads();

    // ---- pooled rep: rep[k][h] = sum_l proj[kh][l] * attn[k][l]  -> (B,K,H) ----
    float* orep = out + (size_t)B_ * K_ * L_ + (size_t)b * (K_ * H_);
    for (int kh = wid; kh < K_ * H_; kh += (NT / 32)) {
        int k = kh / H_;
        const float* pk = sProj + kh * L_;
        const float* ak = sScores + k * L_;
        float s = 0.f;
        for (int l = lane; l < L_; l += 32) s += pk[l] * ak[l];
#pragma unroll
        for (int o = 16; o > 0; o >>= 1) s += __shfl_xor_sync(0xffffffffu, s, o);
        if (lane == 0) orep[kh] = s;
    }
}

extern "C" void kernel_launch(void* const* d_in, const int* in_sizes, int n_in,
                              void* d_out, int out_size)
{
    const float* review   = (const float*)d_in[0];
    const float* aspProj  = (const float*)d_in[1];
    const float* aspEmbed = (const float*)d_in[2];
    float* out = (float*)d_out;

    cudaFuncSetAttribute(anr_arl_kernel,
                         cudaFuncAttributeMaxDynamicSharedMemorySize, SMEM_BYTES);
    anr_arl_kernel<<<B_, NT, SMEM_BYTES>>>(review, aspProj, aspEmbed, out);
}